// round 3
// baseline (speedup 1.0000x reference)
#include <cuda_runtime.h>
#include <cuda_bf16.h>
#include <cstdint>

#define S_LEN 8192
#define HID   2048
#define DIN   2048

#define NCTA  128
#define ROWS_PER_CTA 16   // 2048 / 128
#define SCAN_TPB 512

// ---------------- device scratch (no allocation allowed) ----------------
// Referenced ONLY from device code (never passed as a kernel arg from host).
__device__ float     g_xp[(size_t)S_LEN * HID];   // 64 MB input projection
__device__ float     g_h[2][HID];                 // double-buffered hidden state
__device__ unsigned  g_count;                     // monotonic barrier counter

__device__ __forceinline__ void barrier_arrive_release() {
    asm volatile("red.release.gpu.global.add.u32 [%0], %1;"
                 :: "l"(&g_count), "r"(1u) : "memory");
}
__device__ __forceinline__ unsigned barrier_ld_acquire() {
    unsigned v;
    asm volatile("ld.acquire.gpu.global.u32 %0, [%1];"
                 : "=r"(v) : "l"(&g_count) : "memory");
    return v;
}

// ---------------- init: reset per-launch state ----------------
__global__ void init_kernel() {
    int i = blockIdx.x * blockDim.x + threadIdx.x;
    if (i < 2 * HID) ((float*)g_h)[i] = 0.0f;
    if (i == 0) g_count = 0u;
}

// ---------------- x_proj GEMM: g_xp = X @ Wi^T + bi ----------------
// X: [8192, 2048], Wi: [2048, 2048] (row j = output feature, k contiguous)
// Tile 128x128, BK=16, 256 threads, 8x8 register microtile.
#define BM 128
#define BN 128
#define BK 16

__global__ __launch_bounds__(256, 2) void gemm_xproj(
    const float* __restrict__ X,
    const float* __restrict__ Wi,
    const float* __restrict__ bi)
{
    __shared__ float As[BK][BM + 4];  // [k][m], padded stride 132 (16B-aligned rows)
    __shared__ float Bs[BK][BN + 4];

    const int m0 = blockIdx.y * BM;
    const int n0 = blockIdx.x * BN;
    const int tid = threadIdx.x;
    const int tx = tid & 15;      // 0..15 -> n
    const int ty = tid >> 4;      // 0..15 -> m

    const int lrow = tid >> 2;          // 0..63
    const int lk   = (tid & 3) * 4;     // 0,4,8,12

    const float* Ag = X  + (size_t)m0 * DIN;
    const float* Bg = Wi + (size_t)n0 * DIN;

    float acc[8][8];
#pragma unroll
    for (int i = 0; i < 8; i++)
#pragma unroll
        for (int j = 0; j < 8; j++) acc[i][j] = 0.0f;

    for (int kk = 0; kk < DIN; kk += BK) {
#pragma unroll
        for (int q = 0; q < 2; q++) {
            int r = lrow + 64 * q;
            float4 va = *(const float4*)&Ag[(size_t)r * DIN + kk + lk];
            As[lk + 0][r] = va.x; As[lk + 1][r] = va.y;
            As[lk + 2][r] = va.z; As[lk + 3][r] = va.w;
            float4 vb = *(const float4*)&Bg[(size_t)r * DIN + kk + lk];
            Bs[lk + 0][r] = vb.x; Bs[lk + 1][r] = vb.y;
            Bs[lk + 2][r] = vb.z; Bs[lk + 3][r] = vb.w;
        }
        __syncthreads();

#pragma unroll
        for (int k = 0; k < BK; k++) {
            float a[8], b[8];
            *(float4*)&a[0] = *(const float4*)&As[k][ty * 8];
            *(float4*)&a[4] = *(const float4*)&As[k][ty * 8 + 4];
            *(float4*)&b[0] = *(const float4*)&Bs[k][tx * 8];
            *(float4*)&b[4] = *(const float4*)&Bs[k][tx * 8 + 4];
#pragma unroll
            for (int i = 0; i < 8; i++)
#pragma unroll
                for (int j = 0; j < 8; j++)
                    acc[i][j] = fmaf(a[i], b[j], acc[i][j]);
        }
        __syncthreads();
    }

    // epilogue: add bias, store into device-global g_xp (device-symbol access)
#pragma unroll
    for (int i = 0; i < 8; i++) {
        int m = m0 + ty * 8 + i;
#pragma unroll
        for (int j = 0; j < 8; j += 4) {
            int n = n0 + tx * 8 + j;
            float4 v;
            v.x = acc[i][j + 0] + bi[n + 0];
            v.y = acc[i][j + 1] + bi[n + 1];
            v.z = acc[i][j + 2] + bi[n + 2];
            v.w = acc[i][j + 3] + bi[n + 3];
            *(float4*)&g_xp[(size_t)m * HID + n] = v;
        }
    }
}

// ---------------- persistent scan kernel ----------------
// 128 CTAs x 512 threads, Wh register-resident (64 fp32 weights / thread).
// Thread layout: warp w (0..15), lane = rg*8 + kg_lo  (rg 0..3, kg_lo 0..7)
//   kg = w*8 + kg_lo   (0..127)
//   rows handled: bid*16 + rg*4 + r, r=0..3
//   k covered:    kg*4 + i*512 + c, i=0..3, c=0..3  (4 float4s, warp-coalesced)
__global__ __launch_bounds__(SCAN_TPB, 1) void scan_kernel(
    const float* __restrict__ Wh,
    const float* __restrict__ bh,
    float* __restrict__ out,
    int write_tail)
{
    const int bid  = blockIdx.x;
    const int tid  = threadIdx.x;
    const int w    = tid >> 5;
    const int lane = tid & 31;
    const int kg_lo = lane & 7;
    const int rg    = lane >> 3;
    const int kg    = w * 8 + kg_lo;
    const int row0  = bid * ROWS_PER_CTA + rg * 4;

    // preload weights into registers: Wq[r][i] = Wh[row0+r][kg*4 + i*512 .. +3]
    float4 Wq[4][4];
#pragma unroll
    for (int r = 0; r < 4; r++)
#pragma unroll
        for (int i = 0; i < 4; i++)
            Wq[r][i] = *(const float4*)&Wh[(size_t)(row0 + r) * HID + kg * 4 + i * 512];

    __shared__ float red[ROWS_PER_CTA][17];  // [row][warp], pad to kill conflicts
    __shared__ float s_bh[ROWS_PER_CTA];
    if (tid < ROWS_PER_CTA) s_bh[tid] = bh[bid * ROWS_PER_CTA + tid];
    __syncthreads();

    for (int t = 0; t < S_LEN; t++) {
        // load hidden state chunks (L2, bypass L1 — other SMs wrote it)
        const float4* hsrc = (const float4*)g_h[t & 1];
        float4 hv0 = __ldcg(&hsrc[kg +   0]);
        float4 hv1 = __ldcg(&hsrc[kg + 128]);
        float4 hv2 = __ldcg(&hsrc[kg + 256]);
        float4 hv3 = __ldcg(&hsrc[kg + 384]);

        float acc[4] = {0.f, 0.f, 0.f, 0.f};
#pragma unroll
        for (int r = 0; r < 4; r++) {
            acc[r] = fmaf(Wq[r][0].x, hv0.x, acc[r]);
            acc[r] = fmaf(Wq[r][0].y, hv0.y, acc[r]);
            acc[r] = fmaf(Wq[r][0].z, hv0.z, acc[r]);
            acc[r] = fmaf(Wq[r][0].w, hv0.w, acc[r]);
            acc[r] = fmaf(Wq[r][1].x, hv1.x, acc[r]);
            acc[r] = fmaf(Wq[r][1].y, hv1.y, acc[r]);
            acc[r] = fmaf(Wq[r][1].z, hv1.z, acc[r]);
            acc[r] = fmaf(Wq[r][1].w, hv1.w, acc[r]);
            acc[r] = fmaf(Wq[r][2].x, hv2.x, acc[r]);
            acc[r] = fmaf(Wq[r][2].y, hv2.y, acc[r]);
            acc[r] = fmaf(Wq[r][2].z, hv2.z, acc[r]);
            acc[r] = fmaf(Wq[r][2].w, hv2.w, acc[r]);
            acc[r] = fmaf(Wq[r][3].x, hv3.x, acc[r]);
            acc[r] = fmaf(Wq[r][3].y, hv3.y, acc[r]);
            acc[r] = fmaf(Wq[r][3].z, hv3.z, acc[r]);
            acc[r] = fmaf(Wq[r][3].w, hv3.w, acc[r]);
        }

        // reduce across the 8 kg_lo lanes within each rg group
#pragma unroll
        for (int d = 1; d < 8; d <<= 1) {
            acc[0] += __shfl_xor_sync(0xffffffffu, acc[0], d);
            acc[1] += __shfl_xor_sync(0xffffffffu, acc[1], d);
            acc[2] += __shfl_xor_sync(0xffffffffu, acc[2], d);
            acc[3] += __shfl_xor_sync(0xffffffffu, acc[3], d);
        }
        if (kg_lo == 0) {
            red[rg * 4 + 0][w] = acc[0];
            red[rg * 4 + 1][w] = acc[1];
            red[rg * 4 + 2][w] = acc[2];
            red[rg * 4 + 3][w] = acc[3];
        }
        __syncthreads();

        if (tid < ROWS_PER_CTA) {
            float s = 0.f;
#pragma unroll
            for (int i = 0; i < 16; i++) s += red[tid][i];
            int j = bid * ROWS_PER_CTA + tid;
            float v = tanhf(s + s_bh[tid] + g_xp[(size_t)t * HID + j]);
            out[(size_t)t * HID + j] = v;
            __stcg(&g_h[(t + 1) & 1][j], v);   // L2-visible store for peer SMs
            __threadfence();
        }
        __syncthreads();

        // grid barrier: monotonic counter, release-arrive / acquire-spin
        if (tid == 0) {
            __threadfence();
            barrier_arrive_release();
            unsigned target = (unsigned)(t + 1) * NCTA;
            while (barrier_ld_acquire() < target) { }
            __threadfence();
        }
        __syncthreads();
    }

    // final hidden state h_n = outputs[S-1] (lives in g_h[0] after step 8191)
    if (write_tail && tid < ROWS_PER_CTA) {
        int j = bid * ROWS_PER_CTA + tid;
        out[(size_t)S_LEN * HID + j] = __ldcg(&g_h[0][j]);
    }
}

// ---------------- launch ----------------
extern "C" void kernel_launch(void* const* d_in, const int* in_sizes, int n_in,
                              void* d_out, int out_size) {
    const float* x  = (const float*)d_in[0];
    const float* Wi = (const float*)d_in[1];
    const float* bi = (const float*)d_in[2];
    const float* Wh = (const float*)d_in[3];
    const float* bh = (const float*)d_in[4];
    float* out = (float*)d_out;

    init_kernel<<<(2 * HID + 255) / 256, 256>>>();
    gemm_xproj<<<dim3(HID / BN, S_LEN / BM), 256>>>(x, Wi, bi);

    int write_tail = (out_size >= S_LEN * HID + HID) ? 1 : 0;
    scan_kernel<<<NCTA, SCAN_TPB>>>(Wh, bh, out, write_tail);
}

// round 4
// speedup vs baseline: 1.4050x; 1.4050x over previous
#include <cuda_runtime.h>
#include <cuda_bf16.h>
#include <cstdint>

#define S_LEN 8192
#define HID   2048
#define DIN   2048

#define NCTA  128
#define ROWS_PER_CTA 16   // 2048 / 128
#define SCAN_TPB 512

// ---------------- device scratch (no allocation allowed) ----------------
// Referenced ONLY from device code (never passed as a kernel arg from host).
__device__ float     g_xp[(size_t)S_LEN * HID];   // 64 MB input projection
__device__ float     g_h[2][HID];                 // double-buffered hidden state
__device__ unsigned  g_count;                     // monotonic barrier counter

__device__ __forceinline__ void barrier_arrive_release() {
    asm volatile("red.release.gpu.global.add.u32 [%0], %1;"
                 :: "l"(&g_count), "r"(1u) : "memory");
}
__device__ __forceinline__ unsigned barrier_ld_acquire() {
    unsigned v;
    asm volatile("ld.acquire.gpu.global.u32 %0, [%1];"
                 : "=r"(v) : "l"(&g_count) : "memory");
    return v;
}

// packed fp32x2 FMA (sm_100+ FFMA2 path — only reachable via PTX)
__device__ __forceinline__ unsigned long long fma_f32x2(
    unsigned long long a, unsigned long long b, unsigned long long c) {
    unsigned long long d;
    asm("fma.rn.f32x2 %0, %1, %2, %3;" : "=l"(d) : "l"(a), "l"(b), "l"(c));
    return d;
}

// ---------------- init: reset per-launch state ----------------
__global__ void init_kernel() {
    int i = blockIdx.x * blockDim.x + threadIdx.x;
    if (i < 2 * HID) ((float*)g_h)[i] = 0.0f;
    if (i == 0) g_count = 0u;
}

// ---------------- x_proj GEMM: g_xp = X @ Wi^T + bi ----------------
#define BM 128
#define BN 128
#define BK 16

__global__ __launch_bounds__(256, 2) void gemm_xproj(
    const float* __restrict__ X,
    const float* __restrict__ Wi,
    const float* __restrict__ bi)
{
    __shared__ float As[BK][BM + 4];
    __shared__ float Bs[BK][BN + 4];

    const int m0 = blockIdx.y * BM;
    const int n0 = blockIdx.x * BN;
    const int tid = threadIdx.x;
    const int tx = tid & 15;
    const int ty = tid >> 4;

    const int lrow = tid >> 2;
    const int lk   = (tid & 3) * 4;

    const float* Ag = X  + (size_t)m0 * DIN;
    const float* Bg = Wi + (size_t)n0 * DIN;

    float acc[8][8];
#pragma unroll
    for (int i = 0; i < 8; i++)
#pragma unroll
        for (int j = 0; j < 8; j++) acc[i][j] = 0.0f;

    for (int kk = 0; kk < DIN; kk += BK) {
#pragma unroll
        for (int q = 0; q < 2; q++) {
            int r = lrow + 64 * q;
            float4 va = *(const float4*)&Ag[(size_t)r * DIN + kk + lk];
            As[lk + 0][r] = va.x; As[lk + 1][r] = va.y;
            As[lk + 2][r] = va.z; As[lk + 3][r] = va.w;
            float4 vb = *(const float4*)&Bg[(size_t)r * DIN + kk + lk];
            Bs[lk + 0][r] = vb.x; Bs[lk + 1][r] = vb.y;
            Bs[lk + 2][r] = vb.z; Bs[lk + 3][r] = vb.w;
        }
        __syncthreads();

#pragma unroll
        for (int k = 0; k < BK; k++) {
            float a[8], b[8];
            *(float4*)&a[0] = *(const float4*)&As[k][ty * 8];
            *(float4*)&a[4] = *(const float4*)&As[k][ty * 8 + 4];
            *(float4*)&b[0] = *(const float4*)&Bs[k][tx * 8];
            *(float4*)&b[4] = *(const float4*)&Bs[k][tx * 8 + 4];
#pragma unroll
            for (int i = 0; i < 8; i++)
#pragma unroll
                for (int j = 0; j < 8; j++)
                    acc[i][j] = fmaf(a[i], b[j], acc[i][j]);
        }
        __syncthreads();
    }

#pragma unroll
    for (int i = 0; i < 8; i++) {
        int m = m0 + ty * 8 + i;
#pragma unroll
        for (int j = 0; j < 8; j += 4) {
            int n = n0 + tx * 8 + j;
            float4 v;
            v.x = acc[i][j + 0] + bi[n + 0];
            v.y = acc[i][j + 1] + bi[n + 1];
            v.z = acc[i][j + 2] + bi[n + 2];
            v.w = acc[i][j + 3] + bi[n + 3];
            *(float4*)&g_xp[(size_t)m * HID + n] = v;
        }
    }
}

// ---------------- persistent scan kernel ----------------
// 128 CTAs x 512 threads, Wh register-resident (64 fp32 / thread, packed f32x2).
// warp w (0..15), lane = rg*8 + kg_lo; kg = w*8+kg_lo (0..127)
// rows: bid*16 + rg*4 + r;  k: kg*4 + i*512 + c  (4 float4s, warp-coalesced)
__global__ __launch_bounds__(SCAN_TPB, 1) void scan_kernel(
    const float* __restrict__ Wh,
    const float* __restrict__ bh,
    float* __restrict__ out,
    int write_tail)
{
    const int bid  = blockIdx.x;
    const int tid  = threadIdx.x;
    const int w    = tid >> 5;
    const int lane = tid & 31;
    const int kg_lo = lane & 7;
    const int rg    = lane >> 3;
    const int kg    = w * 8 + kg_lo;
    const int row0  = bid * ROWS_PER_CTA + rg * 4;

    typedef unsigned long long ull;
    union Pk { float4 f; ull u[2]; };

    // preload weights, packed as f32x2: Wp[r][2i],Wp[r][2i+1] pair with h-chunk i
    ull Wp[4][8];
#pragma unroll
    for (int r = 0; r < 4; r++)
#pragma unroll
        for (int i = 0; i < 4; i++) {
            Pk v;
            v.f = *(const float4*)&Wh[(size_t)(row0 + r) * HID + kg * 4 + i * 512];
            Wp[r][2 * i]     = v.u[0];
            Wp[r][2 * i + 1] = v.u[1];
        }

    __shared__ float red[ROWS_PER_CTA][17];
    __shared__ float s_bh[ROWS_PER_CTA];
    if (tid < ROWS_PER_CTA) s_bh[tid] = bh[bid * ROWS_PER_CTA + tid];
    __syncthreads();

    for (int t = 0; t < S_LEN; t++) {
        // prefetch this step's xp value early (warp w handles row w; broadcast load)
        float xpv = __ldcs(&g_xp[(size_t)t * HID + bid * ROWS_PER_CTA + w]);

        // hidden state chunks (L2, bypass L1 — other SMs wrote it)
        const float4* hsrc = (const float4*)g_h[t & 1];
        Pk h0, h1, h2, h3;
        h0.f = __ldcg(&hsrc[kg +   0]);
        h1.f = __ldcg(&hsrc[kg + 128]);
        h2.f = __ldcg(&hsrc[kg + 256]);
        h3.f = __ldcg(&hsrc[kg + 384]);
        ull hp[8] = { h0.u[0], h0.u[1], h1.u[0], h1.u[1],
                      h2.u[0], h2.u[1], h3.u[0], h3.u[1] };

        ull a2[4] = {0ull, 0ull, 0ull, 0ull};
#pragma unroll
        for (int r = 0; r < 4; r++)
#pragma unroll
            for (int i = 0; i < 8; i++)
                a2[r] = fma_f32x2(Wp[r][i], hp[i], a2[r]);

        float acc[4];
#pragma unroll
        for (int r = 0; r < 4; r++) {
            unsigned lo = (unsigned)(a2[r] & 0xffffffffu);
            unsigned hi = (unsigned)(a2[r] >> 32);
            acc[r] = __uint_as_float(lo) + __uint_as_float(hi);
        }

        // reduce across the 8 kg_lo lanes within each rg group
#pragma unroll
        for (int d = 1; d < 8; d <<= 1) {
            acc[0] += __shfl_xor_sync(0xffffffffu, acc[0], d);
            acc[1] += __shfl_xor_sync(0xffffffffu, acc[1], d);
            acc[2] += __shfl_xor_sync(0xffffffffu, acc[2], d);
            acc[3] += __shfl_xor_sync(0xffffffffu, acc[3], d);
        }
        if (kg_lo == 0) {
            red[rg * 4 + 0][w] = acc[0];
            red[rg * 4 + 1][w] = acc[1];
            red[rg * 4 + 2][w] = acc[2];
            red[rg * 4 + 3][w] = acc[3];
        }
        __syncthreads();

        // warp w finishes row w: 16 partials -> shfl tree -> tanh -> stores
        {
            float s = red[w][lane & 15];
            s += __shfl_xor_sync(0xffffffffu, s, 1);
            s += __shfl_xor_sync(0xffffffffu, s, 2);
            s += __shfl_xor_sync(0xffffffffu, s, 4);
            s += __shfl_xor_sync(0xffffffffu, s, 8);
            if (lane == 0) {
                int j = bid * ROWS_PER_CTA + w;
                float v = tanhf(s + s_bh[w] + xpv);
                __stcs(&out[(size_t)t * HID + j], v);
                __stcg(&g_h[(t + 1) & 1][j], v);   // L2-visible for peer SMs
            }
        }
        __syncthreads();

        // grid barrier: monotonic counter, release-arrive / acquire-spin
        if (tid == 0) {
            barrier_arrive_release();
            unsigned target = (unsigned)(t + 1) * NCTA;
            while (barrier_ld_acquire() < target) { }
        }
        __syncthreads();
    }

    // final hidden state h_n = outputs[S-1] (lives in g_h[0] after step 8191)
    if (write_tail && tid < ROWS_PER_CTA) {
        int j = bid * ROWS_PER_CTA + tid;
        out[(size_t)S_LEN * HID + j] = __ldcg(&g_h[0][j]);
    }
}

// ---------------- launch ----------------
extern "C" void kernel_launch(void* const* d_in, const int* in_sizes, int n_in,
                              void* d_out, int out_size) {
    const float* x  = (const float*)d_in[0];
    const float* Wi = (const float*)d_in[1];
    const float* bi = (const float*)d_in[2];
    const float* Wh = (const float*)d_in[3];
    const float* bh = (const float*)d_in[4];
    float* out = (float*)d_out;

    init_kernel<<<(2 * HID + 255) / 256, 256>>>();
    gemm_xproj<<<dim3(HID / BN, S_LEN / BM), 256>>>(x, Wi, bi);

    int write_tail = (out_size >= S_LEN * HID + HID) ? 1 : 0;
    scan_kernel<<<NCTA, SCAN_TPB>>>(Wh, bh, out, write_tail);
}